// round 3
// baseline (speedup 1.0000x reference)
#include <cuda_runtime.h>

#define NNODE 50000
#define NEDGE 800000
#define HD 128
#define NLAYER 4
#define K1 257          // 2H+1
#define TE 64           // edges/nodes per block tile
#define XP 68           // padded tile row (floats), 272B = 16B-aligned

__device__ float g_h[NNODE * HD];
__device__ float g_agg[NNODE * HD];
__device__ float g_d2[NEDGE];

// ---- packed f32x2 helpers (sm_103a) ----
__device__ __forceinline__ void fma2(unsigned long long& a,
                                     unsigned long long x,
                                     unsigned long long w) {
    asm("fma.rn.f32x2 %0, %1, %2, %3;" : "=l"(a) : "l"(x), "l"(w), "l"(a));
}
__device__ __forceinline__ unsigned long long bcast2(float w) {
    unsigned long long r;
    asm("mov.b64 %0, {%1, %1};" : "=l"(r) : "r"(__float_as_uint(w)));
    return r;
}
__device__ __forceinline__ float2 unpack2(unsigned long long a) {
    unsigned lo, hi;
    asm("mov.b64 {%0, %1}, %2;" : "=r"(lo), "=r"(hi) : "l"(a));
    return make_float2(__uint_as_float(lo), __uint_as_float(hi));
}
__device__ __forceinline__ float silu(float x) {
    return x / (1.0f + __expf(-x));
}

// h = emb[z]; agg = 0
__global__ void k_init(const int* __restrict__ z, const float* __restrict__ emb) {
    int i = blockIdx.x * 256 + threadIdx.x;
    if (i < NNODE * HD) {
        g_h[i] = emb[(z[i >> 7] << 7) | (i & 127)];
        g_agg[i] = 0.0f;
    }
}

// d2[e] = ||pos[row]-pos[col]||^2 (loop-invariant)
__global__ void k_d2(const float* __restrict__ pos, const int* __restrict__ ei) {
    int e = blockIdx.x * 256 + threadIdx.x;
    if (e < NEDGE) {
        int r = ei[e], c = ei[NEDGE + e];
        float dx = pos[3 * r + 0] - pos[3 * c + 0];
        float dy = pos[3 * r + 1] - pos[3 * c + 1];
        float dz = pos[3 * r + 2] - pos[3 * c + 2];
        g_d2[e] = dx * dx + dy * dy + dz * dz;
    }
}

// Edge MLP: m = silu(silu([h_row, h_col, d2] @ W1 + b1) @ W2 + b2); agg[row] += m
// 64 edges x 128 cols per block; 256 threads = (col j, edge-half h); 32 edges/thread.
// GEMM1 output tile aliases xs rows 0..127 (dead after GEMM1 barrier).
__global__ __launch_bounds__(256) void k_edge(
    const int* __restrict__ ei,
    const float* __restrict__ W1, const float* __restrict__ b1,
    const float* __restrict__ W2, const float* __restrict__ b2)
{
    __shared__ __align__(16) float xs[K1][XP];   // ~70KB
    __shared__ int srow[TE];
    __shared__ int scol[TE];

    const int tid = threadIdx.x;
    const int warp = tid >> 5, lane = tid & 31;
    const int e0 = blockIdx.x * TE;

    if (tid < TE) srow[tid] = ei[e0 + tid];
    else if (tid < 2 * TE) scol[tid - TE] = ei[NEDGE + e0 + (tid - TE)];
    else if (tid < 3 * TE) xs[256][tid - 2 * TE] = g_d2[e0 + (tid - 2 * TE)];
    __syncthreads();

    // gather h rows -> transposed xs[k][e]
    for (int r = warp; r < 2 * TE; r += 8) {
        int e = r & (TE - 1);
        int node = (r < TE) ? srow[e] : scol[e];
        const float* src = g_h + (size_t)node * HD;
        int kb = (r < TE) ? 0 : HD;
        #pragma unroll
        for (int s = 0; s < 4; s++)
            xs[kb + lane + 32 * s][e] = src[lane + 32 * s];
    }
    __syncthreads();

    const int j  = tid & 127;          // output column
    const int eo = (tid >> 7) << 5;    // edge offset: 0 or 32
    unsigned long long acc[16];

    // GEMM1: [64 x 257] @ [257 x 128]
    #pragma unroll
    for (int q = 0; q < 16; q++) acc[q] = 0ULL;
    {
        const float* wp = W1 + j;
        #pragma unroll 2
        for (int k = 0; k < K1; k++) {
            unsigned long long w2 = bcast2(__ldg(wp + (size_t)k * HD));
            const ulonglong2* xr = (const ulonglong2*)&xs[k][eo];
            #pragma unroll
            for (int q = 0; q < 8; q++) {
                ulonglong2 p = xr[q];
                fma2(acc[2 * q + 0], p.x, w2);
                fma2(acc[2 * q + 1], p.y, w2);
            }
        }
    }
    __syncthreads();   // xs now dead; write activated tile over rows 0..127
    {
        float bb = __ldg(b1 + j);
        #pragma unroll
        for (int q = 0; q < 16; q++) {
            float2 v = unpack2(acc[q]);
            xs[j][eo + 2 * q + 0] = silu(v.x + bb);
            xs[j][eo + 2 * q + 1] = silu(v.y + bb);
        }
    }
    __syncthreads();

    // GEMM2: [64 x 128] @ [128 x 128]
    #pragma unroll
    for (int q = 0; q < 16; q++) acc[q] = 0ULL;
    {
        const float* wp = W2 + j;
        #pragma unroll 2
        for (int k = 0; k < HD; k++) {
            unsigned long long w2 = bcast2(__ldg(wp + (size_t)k * HD));
            const ulonglong2* xr = (const ulonglong2*)&xs[k][eo];
            #pragma unroll
            for (int q = 0; q < 8; q++) {
                ulonglong2 p = xr[q];
                fma2(acc[2 * q + 0], p.x, w2);
                fma2(acc[2 * q + 1], p.y, w2);
            }
        }
    }
    {
        float bb = __ldg(b2 + j);
        #pragma unroll
        for (int q = 0; q < 16; q++) {
            float2 v = unpack2(acc[q]);
            float m0 = silu(v.x + bb);
            float m1 = silu(v.y + bb);
            atomicAdd(&g_agg[(size_t)srow[eo + 2 * q + 0] * HD + j], m0);
            atomicAdd(&g_agg[(size_t)srow[eo + 2 * q + 1] * HD + j], m1);
        }
    }
}

// Node MLP + residual + LayerNorm. 64 nodes per block, 256 threads.
// GEMM1 output aliases xs rows 128..255 (agg half, dead after GEMM1).
// xs rows 0..127 (h) kept live for the residual.
__global__ __launch_bounds__(256) void k_node(
    const float* __restrict__ W1, const float* __restrict__ b1,
    const float* __restrict__ W2, const float* __restrict__ b2,
    const float* __restrict__ lng, const float* __restrict__ lnb,
    float* __restrict__ out, int use_out)
{
    __shared__ __align__(16) float xs[2 * HD][XP];  // ~70KB
    __shared__ float ys[TE][132];                   // ~34KB (LN transpose)

    const int tid = threadIdx.x;
    const int warp = tid >> 5, lane = tid & 31;
    const int n0 = blockIdx.x * TE;

    // gather [h | agg] -> xs[k][e]  (clamped for partial last block)
    for (int r = warp; r < 2 * TE; r += 8) {
        int e = r & (TE - 1);
        int node = n0 + e;
        if (node >= NNODE) node = 0;
        const float* src = (r < TE) ? (g_h + (size_t)node * HD)
                                    : (g_agg + (size_t)node * HD);
        int kb = (r < TE) ? 0 : HD;
        #pragma unroll
        for (int s = 0; s < 4; s++)
            xs[kb + lane + 32 * s][e] = src[lane + 32 * s];
    }
    __syncthreads();

    const int j  = tid & 127;
    const int eo = (tid >> 7) << 5;

    // zero agg rows for next layer (block exclusively owns them)
    #pragma unroll
    for (int q = 0; q < 32; q++) {
        int node = n0 + eo + q;
        if (node < NNODE) g_agg[(size_t)node * HD + j] = 0.0f;
    }

    unsigned long long acc[16];

    // GEMM1: [64 x 256] @ [256 x 128], silu
    #pragma unroll
    for (int q = 0; q < 16; q++) acc[q] = 0ULL;
    {
        const float* wp = W1 + j;
        #pragma unroll 2
        for (int k = 0; k < 2 * HD; k++) {
            unsigned long long w2 = bcast2(__ldg(wp + (size_t)k * HD));
            const ulonglong2* xr = (const ulonglong2*)&xs[k][eo];
            #pragma unroll
            for (int q = 0; q < 8; q++) {
                ulonglong2 p = xr[q];
                fma2(acc[2 * q + 0], p.x, w2);
                fma2(acc[2 * q + 1], p.y, w2);
            }
        }
    }
    __syncthreads();   // agg half of xs now dead; activated tile -> rows 128..255
    {
        float bb = __ldg(b1 + j);
        #pragma unroll
        for (int q = 0; q < 16; q++) {
            float2 v = unpack2(acc[q]);
            xs[HD + j][eo + 2 * q + 0] = silu(v.x + bb);
            xs[HD + j][eo + 2 * q + 1] = silu(v.y + bb);
        }
    }
    __syncthreads();

    // GEMM2: [64 x 128] @ [128 x 128]; + residual from xs rows 0..127
    #pragma unroll
    for (int q = 0; q < 16; q++) acc[q] = 0ULL;
    {
        const float* wp = W2 + j;
        #pragma unroll 2
        for (int k = 0; k < HD; k++) {
            unsigned long long w2 = bcast2(__ldg(wp + (size_t)k * HD));
            const ulonglong2* xr = (const ulonglong2*)&xs[HD + k][eo];
            #pragma unroll
            for (int q = 0; q < 8; q++) {
                ulonglong2 p = xr[q];
                fma2(acc[2 * q + 0], p.x, w2);
                fma2(acc[2 * q + 1], p.y, w2);
            }
        }
    }
    {
        float bb = __ldg(b2 + j);
        #pragma unroll
        for (int q = 0; q < 16; q++) {
            float2 v = unpack2(acc[q]);
            ys[eo + 2 * q + 0][j] = v.x + bb + xs[j][eo + 2 * q + 0];
            ys[eo + 2 * q + 1][j] = v.y + bb + xs[j][eo + 2 * q + 1];
        }
    }
    __syncthreads();

    // LayerNorm: each warp handles 8 nodes
    float* hout = use_out ? out : g_h;
    #pragma unroll
    for (int t = 0; t < 8; t++) {
        int e = warp * 8 + t;
        int node = n0 + e;
        float v0 = ys[e][lane +  0];
        float v1 = ys[e][lane + 32];
        float v2 = ys[e][lane + 64];
        float v3 = ys[e][lane + 96];
        float s  = v0 + v1 + v2 + v3;
        float ss = fmaf(v0, v0, fmaf(v1, v1, fmaf(v2, v2, v3 * v3)));
        #pragma unroll
        for (int o = 16; o; o >>= 1) {
            s  += __shfl_xor_sync(0xffffffffu, s, o);
            ss += __shfl_xor_sync(0xffffffffu, ss, o);
        }
        float mu  = s * (1.0f / 128.0f);
        float inv = rsqrtf(ss * (1.0f / 128.0f) - mu * mu + 1e-5f);
        if (node < NNODE) {
            float* dst = hout + (size_t)node * HD;
            dst[lane +  0] = fmaf(__ldg(lng + lane +  0), (v0 - mu) * inv, __ldg(lnb + lane +  0));
            dst[lane + 32] = fmaf(__ldg(lng + lane + 32), (v1 - mu) * inv, __ldg(lnb + lane + 32));
            dst[lane + 64] = fmaf(__ldg(lng + lane + 64), (v2 - mu) * inv, __ldg(lnb + lane + 64));
            dst[lane + 96] = fmaf(__ldg(lng + lane + 96), (v3 - mu) * inv, __ldg(lnb + lane + 96));
        }
    }
}

extern "C" void kernel_launch(void* const* d_in, const int* in_sizes, int n_in,
                              void* d_out, int out_size) {
    const int*   z   = (const int*)d_in[0];
    const float* pos = (const float*)d_in[1];
    const int*   ei  = (const int*)d_in[2];
    const float* emb = (const float*)d_in[3];
    const float* ew1 = (const float*)d_in[4];
    const float* eb1 = (const float*)d_in[5];
    const float* ew2 = (const float*)d_in[6];
    const float* eb2 = (const float*)d_in[7];
    const float* nw1 = (const float*)d_in[8];
    const float* nb1 = (const float*)d_in[9];
    const float* nw2 = (const float*)d_in[10];
    const float* nb2 = (const float*)d_in[11];
    const float* lng = (const float*)d_in[12];
    const float* lnb = (const float*)d_in[13];
    float* out = (float*)d_out;

    k_init<<<(NNODE * HD + 255) / 256, 256>>>(z, emb);
    k_d2<<<(NEDGE + 255) / 256, 256>>>(pos, ei);

    const int egrid = NEDGE / TE;               // 12500
    const int ngrid = (NNODE + TE - 1) / TE;    // 782

    for (int l = 0; l < NLAYER; l++) {
        k_edge<<<egrid, 256>>>(ei,
                               ew1 + (size_t)l * K1 * HD, eb1 + l * HD,
                               ew2 + (size_t)l * HD * HD, eb2 + l * HD);
        k_node<<<ngrid, 256>>>(nw1 + (size_t)l * 2 * HD * HD, nb1 + l * HD,
                               nw2 + (size_t)l * HD * HD,     nb2 + l * HD,
                               lng + l * HD, lnb + l * HD,
                               out, (l == NLAYER - 1) ? 1 : 0);
    }
}

// round 5
// speedup vs baseline: 2.0582x; 2.0582x over previous
#include <cuda_runtime.h>

#define NNODE 50000
#define NEDGE 800000
#define HD 128
#define NLAYER 4
#define TE 64           // edges per edge-block
#define TN 32           // nodes per pq-block
#define XP 68           // padded tile row (floats) for 64-wide tiles
#define XPN 36          // padded tile row for 32-wide tiles

__device__ float g_h[NNODE * HD];
__device__ float g_agg[NNODE * HD];
__device__ float g_P[NNODE * HD];
__device__ float g_Q[NNODE * HD];
__device__ float g_d2[NEDGE];

// ---- packed f32x2 helpers (sm_103a) ----
__device__ __forceinline__ void fma2(unsigned long long& a,
                                     unsigned long long x,
                                     unsigned long long w) {
    asm("fma.rn.f32x2 %0, %1, %2, %3;" : "=l"(a) : "l"(x), "l"(w), "l"(a));
}
__device__ __forceinline__ unsigned long long bcast2(float w) {
    unsigned long long r;
    asm("mov.b64 %0, {%1, %1};" : "=l"(r) : "r"(__float_as_uint(w)));
    return r;
}
__device__ __forceinline__ float2 unpack2(unsigned long long a) {
    unsigned lo, hi;
    asm("mov.b64 {%0, %1}, %2;" : "=r"(lo), "=r"(hi) : "l"(a));
    return make_float2(__uint_as_float(lo), __uint_as_float(hi));
}
__device__ __forceinline__ float silu(float x) {
    return x / (1.0f + __expf(-x));
}

// h = emb[z]; agg = 0
__global__ void k_init(const int* __restrict__ z, const float* __restrict__ emb) {
    int i = blockIdx.x * 256 + threadIdx.x;
    if (i < NNODE * HD) {
        g_h[i] = emb[(z[i >> 7] << 7) | (i & 127)];
        g_agg[i] = 0.0f;
    }
}

// d2[e] = ||pos[row]-pos[col]||^2 (loop-invariant)
__global__ void k_d2(const float* __restrict__ pos, const int* __restrict__ ei) {
    int e = blockIdx.x * 256 + threadIdx.x;
    if (e < NEDGE) {
        int r = ei[e], c = ei[NEDGE + e];
        float dx = pos[3 * r + 0] - pos[3 * c + 0];
        float dy = pos[3 * r + 1] - pos[3 * c + 1];
        float dz = pos[3 * r + 2] - pos[3 * c + 2];
        g_d2[e] = dx * dx + dy * dy + dz * dz;
    }
}

// P = h @ W1[0:128], Q = h @ W1[128:256]   (32 nodes per block, 256 threads)
// thread = (col j, which-table g); 16 packed accumulators = 32 nodes.
__global__ __launch_bounds__(256) void k_pq(const float* __restrict__ W1) {
    __shared__ __align__(16) float xs[HD][XPN];   // h rows transposed, 18.4KB

    const int tid = threadIdx.x;
    const int warp = tid >> 5, lane = tid & 31;
    const int n0 = blockIdx.x * TN;

    for (int r = warp; r < TN; r += 8) {
        int node = n0 + r;
        if (node >= NNODE) node = NNODE - 1;
        const float* src = g_h + (size_t)node * HD;
        #pragma unroll
        for (int s = 0; s < 4; s++)
            xs[lane + 32 * s][r] = src[lane + 32 * s];
    }
    __syncthreads();

    const int j = tid & 127;
    const int g = tid >> 7;            // 0 -> P, 1 -> Q
    const float* wp = W1 + (size_t)(g * 128) * HD + j;

    unsigned long long acc[16];
    #pragma unroll
    for (int q = 0; q < 16; q++) acc[q] = 0ULL;
    #pragma unroll 4
    for (int k = 0; k < HD; k++) {
        unsigned long long w2 = bcast2(__ldg(wp + (size_t)k * HD));
        const ulonglong2* xr = (const ulonglong2*)&xs[k][0];
        #pragma unroll
        for (int q = 0; q < 8; q++) {
            ulonglong2 p = xr[q];
            fma2(acc[2 * q + 0], p.x, w2);
            fma2(acc[2 * q + 1], p.y, w2);
        }
    }
    float* dst = g ? g_Q : g_P;
    #pragma unroll
    for (int q = 0; q < 16; q++) {
        float2 v = unpack2(acc[q]);
        int n0e = n0 + 2 * q;
        if (n0e < NNODE)     dst[(size_t)n0e * HD + j]       = v.x;
        if (n0e + 1 < NNODE) dst[(size_t)(n0e + 1) * HD + j] = v.y;
    }
}

// Edge: u = silu(P[row] + Q[col] + d2*w1_last + b1); m = silu(u @ W2 + b2);
//       agg[row] += m.   64 edges x 128 cols, 256 threads.
__global__ __launch_bounds__(256) void k_edge(
    const int* __restrict__ ei,
    const float* __restrict__ W1,            // for row 256 (d2 weights)
    const float* __restrict__ b1,
    const float* __restrict__ W2, const float* __restrict__ b2)
{
    __shared__ __align__(16) float xs[HD][XP];   // u transposed, 34.8KB
    __shared__ int srow[TE], scol[TE];
    __shared__ float sd2[TE], s_b1[HD], s_wl[HD];

    const int tid = threadIdx.x;
    const int warp = tid >> 5, lane = tid & 31;
    const int e0 = blockIdx.x * TE;

    if (tid < TE) { srow[tid] = ei[e0 + tid]; sd2[tid] = g_d2[e0 + tid]; }
    else if (tid < 2 * TE) scol[tid - TE] = ei[NEDGE + e0 + (tid - TE)];
    if (tid < HD) {
        s_b1[tid] = __ldg(b1 + tid);
        s_wl[tid] = __ldg(W1 + 256 * HD + tid);
    }
    __syncthreads();

    // gather + add + silu -> xs[k][e]
    for (int r = warp; r < TE; r += 8) {
        const float* pp = g_P + (size_t)srow[r] * HD;
        const float* qq = g_Q + (size_t)scol[r] * HD;
        float d2e = sd2[r];
        #pragma unroll
        for (int s = 0; s < 4; s++) {
            int k = lane + 32 * s;
            float u = __ldg(pp + k) + __ldg(qq + k) + d2e * s_wl[k] + s_b1[k];
            xs[k][r] = silu(u);
        }
    }
    __syncthreads();

    const int j  = tid & 127;          // output column
    const int eo = (tid >> 7) << 5;    // edge offset: 0 or 32
    unsigned long long acc[16];
    #pragma unroll
    for (int q = 0; q < 16; q++) acc[q] = 0ULL;
    {
        const float* wp = W2 + j;
        #pragma unroll 4
        for (int k = 0; k < HD; k++) {
            unsigned long long w2 = bcast2(__ldg(wp + (size_t)k * HD));
            const ulonglong2* xr = (const ulonglong2*)&xs[k][eo];
            #pragma unroll
            for (int q = 0; q < 8; q++) {
                ulonglong2 p = xr[q];
                fma2(acc[2 * q + 0], p.x, w2);
                fma2(acc[2 * q + 1], p.y, w2);
            }
        }
    }
    {
        float bb = __ldg(b2 + j);
        #pragma unroll
        for (int q = 0; q < 16; q++) {
            float2 v = unpack2(acc[q]);
            float m0 = silu(v.x + bb);
            float m1 = silu(v.y + bb);
            atomicAdd(&g_agg[(size_t)srow[eo + 2 * q + 0] * HD + j], m0);
            atomicAdd(&g_agg[(size_t)srow[eo + 2 * q + 1] * HD + j], m1);
        }
    }
}

// Node MLP + residual + LayerNorm. 64 nodes per block, 256 threads.
__global__ __launch_bounds__(256) void k_node(
    const float* __restrict__ W1, const float* __restrict__ b1,
    const float* __restrict__ W2, const float* __restrict__ b2,
    const float* __restrict__ lng, const float* __restrict__ lnb,
    float* __restrict__ out, int use_out)
{
    __shared__ __align__(16) float xs[2 * HD][XP];  // ~70KB
    __shared__ float ys[TE][132];                   // ~34KB (LN transpose)

    const int tid = threadIdx.x;
    const int warp = tid >> 5, lane = tid & 31;
    const int n0 = blockIdx.x * TE;

    // gather [h | agg] -> xs[k][e]
    for (int r = warp; r < 2 * TE; r += 8) {
        int e = r & (TE - 1);
        int node = n0 + e;
        if (node >= NNODE) node = 0;
        const float* src = (r < TE) ? (g_h + (size_t)node * HD)
                                    : (g_agg + (size_t)node * HD);
        int kb = (r < TE) ? 0 : HD;
        #pragma unroll
        for (int s = 0; s < 4; s++)
            xs[kb + lane + 32 * s][e] = src[lane + 32 * s];
    }
    __syncthreads();

    const int j  = tid & 127;
    const int eo = (tid >> 7) << 5;

    // zero agg rows for next layer (block exclusively owns them)
    #pragma unroll
    for (int q = 0; q < 32; q++) {
        int node = n0 + eo + q;
        if (node < NNODE) g_agg[(size_t)node * HD + j] = 0.0f;
    }

    unsigned long long acc[16];

    // GEMM1: [64 x 256] @ [256 x 128], silu
    #pragma unroll
    for (int q = 0; q < 16; q++) acc[q] = 0ULL;
    {
        const float* wp = W1 + j;
        #pragma unroll 2
        for (int k = 0; k < 2 * HD; k++) {
            unsigned long long w2 = bcast2(__ldg(wp + (size_t)k * HD));
            const ulonglong2* xr = (const ulonglong2*)&xs[k][eo];
            #pragma unroll
            for (int q = 0; q < 8; q++) {
                ulonglong2 p = xr[q];
                fma2(acc[2 * q + 0], p.x, w2);
                fma2(acc[2 * q + 1], p.y, w2);
            }
        }
    }
    __syncthreads();   // agg half of xs now dead; activated tile -> rows 128..255
    {
        float bb = __ldg(b1 + j);
        #pragma unroll
        for (int q = 0; q < 16; q++) {
            float2 v = unpack2(acc[q]);
            xs[HD + j][eo + 2 * q + 0] = silu(v.x + bb);
            xs[HD + j][eo + 2 * q + 1] = silu(v.y + bb);
        }
    }
    __syncthreads();

    // GEMM2: [64 x 128] @ [128 x 128]; + residual from xs rows 0..127
    #pragma unroll
    for (int q = 0; q < 16; q++) acc[q] = 0ULL;
    {
        const float* wp = W2 + j;
        #pragma unroll 2
        for (int k = 0; k < HD; k++) {
            unsigned long long w2 = bcast2(__ldg(wp + (size_t)k * HD));
            const ulonglong2* xr = (const ulonglong2*)&xs[HD + k][eo];
            #pragma unroll
            for (int q = 0; q < 8; q++) {
                ulonglong2 p = xr[q];
                fma2(acc[2 * q + 0], p.x, w2);
                fma2(acc[2 * q + 1], p.y, w2);
            }
        }
    }
    {
        float bb = __ldg(b2 + j);
        #pragma unroll
        for (int q = 0; q < 16; q++) {
            float2 v = unpack2(acc[q]);
            ys[eo + 2 * q + 0][j] = v.x + bb + xs[j][eo + 2 * q + 0];
            ys[eo + 2 * q + 1][j] = v.y + bb + xs[j][eo + 2 * q + 1];
        }
    }
    __syncthreads();

    // LayerNorm: each warp handles 8 nodes
    float* hout = use_out ? out : g_h;
    #pragma unroll
    for (int t = 0; t < 8; t++) {
        int e = warp * 8 + t;
        int node = n0 + e;
        float v0 = ys[e][lane +  0];
        float v1 = ys[e][lane + 32];
        float v2 = ys[e][lane + 64];
        float v3 = ys[e][lane + 96];
        float s  = v0 + v1 + v2 + v3;
        float ss = fmaf(v0, v0, fmaf(v1, v1, fmaf(v2, v2, v3 * v3)));
        #pragma unroll
        for (int o = 16; o; o >>= 1) {
            s  += __shfl_xor_sync(0xffffffffu, s, o);
            ss += __shfl_xor_sync(0xffffffffu, ss, o);
        }
        float mu  = s * (1.0f / 128.0f);
        float inv = rsqrtf(ss * (1.0f / 128.0f) - mu * mu + 1e-5f);
        if (node < NNODE) {
            float* dst = hout + (size_t)node * HD;
            dst[lane +  0] = fmaf(__ldg(lng + lane +  0), (v0 - mu) * inv, __ldg(lnb + lane +  0));
            dst[lane + 32] = fmaf(__ldg(lng + lane + 32), (v1 - mu) * inv, __ldg(lnb + lane + 32));
            dst[lane + 64] = fmaf(__ldg(lng + lane + 64), (v2 - mu) * inv, __ldg(lnb + lane + 64));
            dst[lane + 96] = fmaf(__ldg(lng + lane + 96), (v3 - mu) * inv, __ldg(lnb + lane + 96));
        }
    }
}

extern "C" void kernel_launch(void* const* d_in, const int* in_sizes, int n_in,
                              void* d_out, int out_size) {
    const int*   z   = (const int*)d_in[0];
    const float* pos = (const float*)d_in[1];
    const int*   ei  = (const int*)d_in[2];
    const float* emb = (const float*)d_in[3];
    const float* ew1 = (const float*)d_in[4];
    const float* eb1 = (const float*)d_in[5];
    const float* ew2 = (const float*)d_in[6];
    const float* eb2 = (const float*)d_in[7];
    const float* nw1 = (const float*)d_in[8];
    const float* nb1 = (const float*)d_in[9];
    const float* nw2 = (const float*)d_in[10];
    const float* nb2 = (const float*)d_in[11];
    const float* lng = (const float*)d_in[12];
    const float* lnb = (const float*)d_in[13];
    float* out = (float*)d_out;

    k_init<<<(NNODE * HD + 255) / 256, 256>>>(z, emb);
    k_d2<<<(NEDGE + 255) / 256, 256>>>(pos, ei);

    const int pqgrid = (NNODE + TN - 1) / TN;   // 1563
    const int egrid  = NEDGE / TE;              // 12500
    const int ngrid  = (NNODE + TE - 1) / TE;   // 782

    for (int l = 0; l < NLAYER; l++) {
        const float* W1l = ew1 + (size_t)l * 257 * HD;
        k_pq<<<pqgrid, 256>>>(W1l);
        k_edge<<<egrid, 256>>>(ei, W1l, eb1 + l * HD,
                               ew2 + (size_t)l * HD * HD, eb2 + l * HD);
        k_node<<<ngrid, 256>>>(nw1 + (size_t)l * 2 * HD * HD, nb1 + l * HD,
                               nw2 + (size_t)l * HD * HD,     nb2 + l * HD,
                               lng + l * HD, lnb + l * HD,
                               out, (l == NLAYER - 1) ? 1 : 0);
    }
}

// round 6
// speedup vs baseline: 2.7712x; 1.3464x over previous
#include <cuda_runtime.h>

#define NNODE 50000
#define NEDGE 800000
#define HD 128
#define NLAYER 4
#define TE 64           // edges/nodes per block tile
#define TN 32           // nodes per pq-block
#define XP 68           // padded tile row (floats), 272B = 16B-aligned
#define XPN 36          // padded tile row for 32-wide tiles

__device__ float g_h[NNODE * HD];
__device__ float g_agg[NNODE * HD];
__device__ float g_P[NNODE * HD];
__device__ float g_Q[NNODE * HD];
__device__ float g_d2[NEDGE];

// ---- packed f32x2 helpers (sm_103a) ----
__device__ __forceinline__ void fma2(unsigned long long& a,
                                     unsigned long long x,
                                     unsigned long long w) {
    asm("fma.rn.f32x2 %0, %1, %2, %3;" : "=l"(a) : "l"(x), "l"(w), "l"(a));
}
__device__ __forceinline__ unsigned long long bcast2(float w) {
    unsigned long long r;
    asm("mov.b64 %0, {%1, %1};" : "=l"(r) : "r"(__float_as_uint(w)));
    return r;
}
__device__ __forceinline__ float2 unpack2(unsigned long long a) {
    unsigned lo, hi;
    asm("mov.b64 {%0, %1}, %2;" : "=r"(lo), "=r"(hi) : "l"(a));
    return make_float2(__uint_as_float(lo), __uint_as_float(hi));
}
__device__ __forceinline__ float silu(float x) {
    return x / (1.0f + __expf(-x));
}

__global__ void k_init(const int* __restrict__ z, const float* __restrict__ emb) {
    int i = blockIdx.x * 256 + threadIdx.x;
    if (i < NNODE * HD) {
        g_h[i] = emb[(z[i >> 7] << 7) | (i & 127)];
        g_agg[i] = 0.0f;
    }
}

__global__ void k_d2(const float* __restrict__ pos, const int* __restrict__ ei) {
    int e = blockIdx.x * 256 + threadIdx.x;
    if (e < NEDGE) {
        int r = ei[e], c = ei[NEDGE + e];
        float dx = pos[3 * r + 0] - pos[3 * c + 0];
        float dy = pos[3 * r + 1] - pos[3 * c + 1];
        float dz = pos[3 * r + 2] - pos[3 * c + 2];
        g_d2[e] = dx * dx + dy * dy + dz * dz;
    }
}

// P = h @ W1[0:128], Q = h @ W1[128:256]   (32 nodes per block, 256 threads)
// thread = (table g, node-half q2, col-pair cp): 2 cols x 16 nodes.
__global__ __launch_bounds__(256) void k_pq(const float* __restrict__ W1) {
    __shared__ __align__(16) float xs[HD][XPN];

    const int tid = threadIdx.x;
    const int warp = tid >> 5, lane = tid & 31;
    const int n0 = blockIdx.x * TN;

    for (int r = warp; r < TN; r += 8) {
        int node = n0 + r;
        if (node >= NNODE) node = NNODE - 1;
        const float* src = g_h + (size_t)node * HD;
        #pragma unroll
        for (int s = 0; s < 4; s++)
            xs[lane + 32 * s][r] = src[lane + 32 * s];
    }
    __syncthreads();

    const int cp = tid & 63;          // col pair -> cols 2cp, 2cp+1
    const int q2 = (tid >> 6) & 1;    // node half: 16*q2
    const int g  = tid >> 7;          // 0 -> P, 1 -> Q
    const float* wp = W1 + (size_t)(g * 128) * HD + 2 * cp;

    unsigned long long a0[8], a1[8];
    #pragma unroll
    for (int q = 0; q < 8; q++) { a0[q] = 0ULL; a1[q] = 0ULL; }
    #pragma unroll 4
    for (int k = 0; k < HD; k++) {
        float2 w = __ldg((const float2*)(wp + (size_t)k * HD));
        unsigned long long w0 = bcast2(w.x), w1 = bcast2(w.y);
        const ulonglong2* xr = (const ulonglong2*)&xs[k][16 * q2];
        #pragma unroll
        for (int p = 0; p < 4; p++) {
            ulonglong2 pr = xr[p];
            fma2(a0[2*p+0], pr.x, w0); fma2(a0[2*p+1], pr.y, w0);
            fma2(a1[2*p+0], pr.x, w1); fma2(a1[2*p+1], pr.y, w1);
        }
    }
    float* dst = g ? g_Q : g_P;
    #pragma unroll
    for (int p = 0; p < 8; p++) {
        float2 v0 = unpack2(a0[p]);
        float2 v1 = unpack2(a1[p]);
        int na = n0 + 16 * q2 + 2 * p, nb = na + 1;
        if (na < NNODE) {
            dst[(size_t)na * HD + 2 * cp]     = v0.x;
            dst[(size_t)na * HD + 2 * cp + 1] = v1.x;
        }
        if (nb < NNODE) {
            dst[(size_t)nb * HD + 2 * cp]     = v0.y;
            dst[(size_t)nb * HD + 2 * cp + 1] = v1.y;
        }
    }
}

// Edge: u = silu(P[row] + Q[col] + d2*w1_last + b1); m = silu(u @ W2 + b2);
//       agg[row] += m.  64 edges x 128 cols, 256 threads = (quarter q4, colpair cp).
__global__ __launch_bounds__(256) void k_edge(
    const int* __restrict__ ei,
    const float* __restrict__ W1,            // row 256 = d2 weights
    const float* __restrict__ b1,
    const float* __restrict__ W2, const float* __restrict__ b2)
{
    __shared__ __align__(16) float xs[HD][XP];   // u transposed, ~35KB
    __shared__ int srow[TE], scol[TE];
    __shared__ float sd2[TE], s_b1[HD], s_wl[HD];

    const int tid = threadIdx.x;
    const int warp = tid >> 5, lane = tid & 31;
    const int e0 = blockIdx.x * TE;

    if (tid < TE) { srow[tid] = ei[e0 + tid]; sd2[tid] = g_d2[e0 + tid]; }
    else if (tid < 2 * TE) scol[tid - TE] = ei[NEDGE + e0 + (tid - TE)];
    if (tid < HD) {
        s_b1[tid] = __ldg(b1 + tid);
        s_wl[tid] = __ldg(W1 + 256 * HD + tid);
    }
    __syncthreads();

    // gather + add + silu -> xs[k][e]
    for (int r = warp; r < TE; r += 8) {
        const float* pp = g_P + (size_t)srow[r] * HD;
        const float* qq = g_Q + (size_t)scol[r] * HD;
        float d2e = sd2[r];
        #pragma unroll
        for (int s = 0; s < 4; s++) {
            int k = lane + 32 * s;
            float u = __ldg(pp + k) + __ldg(qq + k) + d2e * s_wl[k] + s_b1[k];
            xs[k][r] = silu(u);
        }
    }
    __syncthreads();

    const int cp = tid & 63;          // cols 2cp, 2cp+1
    const int q4 = tid >> 6;          // edges 16*q4 .. 16*q4+15
    const int eb = 16 * q4;
    unsigned long long a0[8], a1[8];
    #pragma unroll
    for (int q = 0; q < 8; q++) { a0[q] = 0ULL; a1[q] = 0ULL; }
    {
        const float* wp = W2 + 2 * cp;
        #pragma unroll 4
        for (int k = 0; k < HD; k++) {
            float2 w = __ldg((const float2*)(wp + (size_t)k * HD));
            unsigned long long w0 = bcast2(w.x), w1 = bcast2(w.y);
            const ulonglong2* xr = (const ulonglong2*)&xs[k][eb];
            #pragma unroll
            for (int p = 0; p < 4; p++) {
                ulonglong2 pr = xr[p];
                fma2(a0[2*p+0], pr.x, w0); fma2(a0[2*p+1], pr.y, w0);
                fma2(a1[2*p+0], pr.x, w1); fma2(a1[2*p+1], pr.y, w1);
            }
        }
    }
    {
        float2 bb = __ldg((const float2*)(b2 + 2 * cp));
        #pragma unroll
        for (int p = 0; p < 8; p++) {
            float2 v0 = unpack2(a0[p]);
            float2 v1 = unpack2(a1[p]);
            int ea = eb + 2 * p;
            float* ra = g_agg + (size_t)srow[ea] * HD;
            float* rb = g_agg + (size_t)srow[ea + 1] * HD;
            atomicAdd(ra + 2 * cp,     silu(v0.x + bb.x));
            atomicAdd(ra + 2 * cp + 1, silu(v1.x + bb.y));
            atomicAdd(rb + 2 * cp,     silu(v0.y + bb.x));
            atomicAdd(rb + 2 * cp + 1, silu(v1.y + bb.y));
        }
    }
}

// Node MLP + residual + LayerNorm. 64 nodes per block, 256 threads.
__global__ __launch_bounds__(256) void k_node(
    const float* __restrict__ W1, const float* __restrict__ b1,
    const float* __restrict__ W2, const float* __restrict__ b2,
    const float* __restrict__ lng, const float* __restrict__ lnb,
    float* __restrict__ out, int use_out)
{
    __shared__ __align__(16) float xs[2 * HD][XP];  // ~70KB
    __shared__ float ys[TE][132];                   // ~34KB

    const int tid = threadIdx.x;
    const int warp = tid >> 5, lane = tid & 31;
    const int n0 = blockIdx.x * TE;

    for (int r = warp; r < 2 * TE; r += 8) {
        int e = r & (TE - 1);
        int node = n0 + e;
        if (node >= NNODE) node = 0;
        const float* src = (r < TE) ? (g_h + (size_t)node * HD)
                                    : (g_agg + (size_t)node * HD);
        int kb = (r < TE) ? 0 : HD;
        #pragma unroll
        for (int s = 0; s < 4; s++)
            xs[kb + lane + 32 * s][e] = src[lane + 32 * s];
    }
    __syncthreads();

    const int cp = tid & 63;
    const int q4 = tid >> 6;
    const int eb = 16 * q4;

    // zero agg rows for next layer (block exclusively owns them)
    {
        int j = tid & 127;
        int ho = (tid >> 7) << 5;
        #pragma unroll
        for (int q = 0; q < 32; q++) {
            int node = n0 + ho + q;
            if (node < NNODE) g_agg[(size_t)node * HD + j] = 0.0f;
        }
    }

    unsigned long long a0[8], a1[8];

    // GEMM1: [64 x 256] @ [256 x 128], silu
    #pragma unroll
    for (int q = 0; q < 8; q++) { a0[q] = 0ULL; a1[q] = 0ULL; }
    {
        const float* wp = W1 + 2 * cp;
        #pragma unroll 4
        for (int k = 0; k < 2 * HD; k++) {
            float2 w = __ldg((const float2*)(wp + (size_t)k * HD));
            unsigned long long w0 = bcast2(w.x), w1 = bcast2(w.y);
            const ulonglong2* xr = (const ulonglong2*)&xs[k][eb];
            #pragma unroll
            for (int p = 0; p < 4; p++) {
                ulonglong2 pr = xr[p];
                fma2(a0[2*p+0], pr.x, w0); fma2(a0[2*p+1], pr.y, w0);
                fma2(a1[2*p+0], pr.x, w1); fma2(a1[2*p+1], pr.y, w1);
            }
        }
    }
    __syncthreads();   // agg half of xs dead; activated tile -> rows 128..255
    {
        float2 bb = __ldg((const float2*)(b1 + 2 * cp));
        #pragma unroll
        for (int p = 0; p < 8; p++) {
            float2 v0 = unpack2(a0[p]);
            float2 v1 = unpack2(a1[p]);
            int ea = eb + 2 * p;
            xs[HD + 2 * cp][ea]         = silu(v0.x + bb.x);
            xs[HD + 2 * cp][ea + 1]     = silu(v0.y + bb.x);
            xs[HD + 2 * cp + 1][ea]     = silu(v1.x + bb.y);
            xs[HD + 2 * cp + 1][ea + 1] = silu(v1.y + bb.y);
        }
    }
    __syncthreads();

    // GEMM2: [64 x 128] @ [128 x 128]; + residual from xs rows 0..127
    #pragma unroll
    for (int q = 0; q < 8; q++) { a0[q] = 0ULL; a1[q] = 0ULL; }
    {
        const float* wp = W2 + 2 * cp;
        #pragma unroll 4
        for (int k = 0; k < HD; k++) {
            float2 w = __ldg((const float2*)(wp + (size_t)k * HD));
            unsigned long long w0 = bcast2(w.x), w1 = bcast2(w.y);
            const ulonglong2* xr = (const ulonglong2*)&xs[HD + k][eb];
            #pragma unroll
            for (int p = 0; p < 4; p++) {
                ulonglong2 pr = xr[p];
                fma2(a0[2*p+0], pr.x, w0); fma2(a0[2*p+1], pr.y, w0);
                fma2(a1[2*p+0], pr.x, w1); fma2(a1[2*p+1], pr.y, w1);
            }
        }
    }
    {
        float2 bb = __ldg((const float2*)(b2 + 2 * cp));
        #pragma unroll
        for (int p = 0; p < 8; p++) {
            float2 v0 = unpack2(a0[p]);
            float2 v1 = unpack2(a1[p]);
            int ea = eb + 2 * p;
            ys[ea][2 * cp]         = v0.x + bb.x + xs[2 * cp][ea];
            ys[ea + 1][2 * cp]     = v0.y + bb.x + xs[2 * cp][ea + 1];
            ys[ea][2 * cp + 1]     = v1.x + bb.y + xs[2 * cp + 1][ea];
            ys[ea + 1][2 * cp + 1] = v1.y + bb.y + xs[2 * cp + 1][ea + 1];
        }
    }
    __syncthreads();

    // LayerNorm: each warp handles 8 nodes
    float* hout = use_out ? out : g_h;
    #pragma unroll
    for (int t = 0; t < 8; t++) {
        int e = warp * 8 + t;
        int node = n0 + e;
        float v0 = ys[e][lane +  0];
        float v1 = ys[e][lane + 32];
        float v2 = ys[e][lane + 64];
        float v3 = ys[e][lane + 96];
        float s  = v0 + v1 + v2 + v3;
        float ss = fmaf(v0, v0, fmaf(v1, v1, fmaf(v2, v2, v3 * v3)));
        #pragma unroll
        for (int o = 16; o; o >>= 1) {
            s  += __shfl_xor_sync(0xffffffffu, s, o);
            ss += __shfl_xor_sync(0xffffffffu, ss, o);
        }
        float mu  = s * (1.0f / 128.0f);
        float inv = rsqrtf(ss * (1.0f / 128.0f) - mu * mu + 1e-5f);
        if (node < NNODE) {
            float* dst = hout + (size_t)node * HD;
            dst[lane +  0] = fmaf(__ldg(lng + lane +  0), (v0 - mu) * inv, __ldg(lnb + lane +  0));
            dst[lane + 32] = fmaf(__ldg(lng + lane + 32), (v1 - mu) * inv, __ldg(lnb + lane + 32));
            dst[lane + 64] = fmaf(__ldg(lng + lane + 64), (v2 - mu) * inv, __ldg(lnb + lane + 64));
            dst[lane + 96] = fmaf(__ldg(lng + lane + 96), (v3 - mu) * inv, __ldg(lnb + lane + 96));
        }
    }
}

extern "C" void kernel_launch(void* const* d_in, const int* in_sizes, int n_in,
                              void* d_out, int out_size) {
    const int*   z   = (const int*)d_in[0];
    const float* pos = (const float*)d_in[1];
    const int*   ei  = (const int*)d_in[2];
    const float* emb = (const float*)d_in[3];
    const float* ew1 = (const float*)d_in[4];
    const float* eb1 = (const float*)d_in[5];
    const float* ew2 = (const float*)d_in[6];
    const float* eb2 = (const float*)d_in[7];
    const float* nw1 = (const float*)d_in[8];
    const float* nb1 = (const float*)d_in[9];
    const float* nw2 = (const float*)d_in[10];
    const float* nb2 = (const float*)d_in[11];
    const float* lng = (const float*)d_in[12];
    const float* lnb = (const float*)d_in[13];
    float* out = (float*)d_out;

    k_init<<<(NNODE * HD + 255) / 256, 256>>>(z, emb);
    k_d2<<<(NEDGE + 255) / 256, 256>>>(pos, ei);

    const int pqgrid = (NNODE + TN - 1) / TN;   // 1563
    const int egrid  = NEDGE / TE;              // 12500
    const int ngrid  = (NNODE + TE - 1) / TE;   // 782

    for (int l = 0; l < NLAYER; l++) {
        const float* W1l = ew1 + (size_t)l * 257 * HD;
        k_pq<<<pqgrid, 256>>>(W1l);
        k_edge<<<egrid, 256>>>(ei, W1l, eb1 + l * HD,
                               ew2 + (size_t)l * HD * HD, eb2 + l * HD);
        k_node<<<ngrid, 256>>>(nw1 + (size_t)l * 2 * HD * HD, nb1 + l * HD,
                               nw2 + (size_t)l * HD * HD,     nb2 + l * HD,
                               lng + l * HD, lnb + l * HD,
                               out, (l == NLAYER - 1) ? 1 : 0);
    }
}